// round 14
// baseline (speedup 1.0000x reference)
#include <cuda_runtime.h>
#include <cuda_fp16.h>
#include <float.h>
#include <math.h>
#include <stdint.h>

#define BATCH   1024
#define DIM     384
#define NCUBES  131072
#define TOPK    16

#define BT      128             // queries per CTA
#define CT      128             // cubes per n-tile
#define KT      64              // int8 elems per k tile (64B rows)
#define NKT     (DIM/KT)        // 6
#define NCHUNK  2048            // cubes per CTA chunk
#define NTILES  (NCHUNK/CT)     // 16
#define NCHUNKS (NCUBES/NCHUNK) // 64
#define BTILES  (BATCH/BT)      // 8
#define NTT     (NTILES*NKT)    // 96
#define NTHREADS 512
#define NSTAGE  4
#define LVP     17
#define RESCORE 48

#define PITCHB  80              // smem row pitch in BYTES (64 + 16 pad; conflict-free)

// ---- stage layout (bytes) ----
#define ST_Q    (BT*PITCHB)           // 10240
#define ST_ED   (CT*PITCHB)           // 10240
#define STAGE   (ST_Q + 2*ST_ED)      // 30720
#define OFF_SC  (NSTAGE*STAGE)        // 122880
#define SC_PITCH 132                  // floats per query row (128 + 4 pad)
#define OFF_SE  (OFF_SC + BT*SC_PITCH*4)   // 190464 : se[NCHUNK] floats
#define OFF_SD  (OFF_SE + NCHUNK*4)        // 198656 : sd[NCHUNK] floats
#define OFF_LV  (OFF_SD + NCHUNK*4)        // 206848
#define OFF_LI  (OFF_LV + BT*LVP*4)        // 215552
#define SMEM_SZ (OFF_LI + BT*LVP*4)        // 224256  (< 227KB limit)

// ---------------- device scratch ----------------
__device__ float   g_qn[BATCH * DIM];          // normalized queries fp32 (rescore)
__device__ int8_t  g_q8[BATCH * DIM];
__device__ int8_t  g_e8[NCUBES * DIM];
__device__ int8_t  g_d8[NCUBES * DIM];
__device__ float   g_se[NCUBES];               // dequant scales (maxabs/127)
__device__ float   g_sd[NCUBES];
__device__ float   g_cand_v[BATCH * NCHUNKS * TOPK];
__device__ int     g_cand_i[BATCH * NCHUNKS * TOPK];

// ---------------- PTX helpers ----------------
__device__ __forceinline__ uint32_t smem_u32(const void* p) {
    uint32_t a;
    asm("{ .reg .u64 t; cvta.to.shared.u64 t, %1; cvt.u32.u64 %0, t; }" : "=r"(a) : "l"(p));
    return a;
}
__device__ __forceinline__ void cp16(uint32_t s, const void* g) {
    asm volatile("cp.async.cg.shared.global [%0], [%1], 16;" :: "r"(s), "l"(g));
}
__device__ __forceinline__ void cp_commit() {
    asm volatile("cp.async.commit_group;");
}
template <int N> __device__ __forceinline__ void cp_wait() {
    asm volatile("cp.async.wait_group %0;" :: "n"(N));
}
__device__ __forceinline__ void ldsm4(uint32_t* r, uint32_t addr) {
    asm volatile("ldmatrix.sync.aligned.m8n8.x4.shared.b16 {%0,%1,%2,%3}, [%4];"
                 : "=r"(r[0]), "=r"(r[1]), "=r"(r[2]), "=r"(r[3]) : "r"(addr));
}
// int8 MMA: D += A(16x32 s8) * B^T(8x32 s8), s32 accum
__device__ __forceinline__ void mma16832s8(int* d, const uint32_t* a, const uint32_t* b) {
    asm volatile("mma.sync.aligned.m16n8k32.row.col.s32.s8.s8.s32 "
                 "{%0,%1,%2,%3}, {%4,%5,%6,%7}, {%8,%9}, {%0,%1,%2,%3};"
                 : "+r"(d[0]), "+r"(d[1]), "+r"(d[2]), "+r"(d[3])
                 : "r"(a[0]), "r"(a[1]), "r"(a[2]), "r"(a[3]),
                   "r"(b[0]), "r"(b[1]));
}

// ---------------- kernel 1: normalize queries (fp32 out) + int8 quantize ----------------
__global__ __launch_bounds__(128) void norm_q_kernel(const float* __restrict__ q) {
    int b = blockIdx.x;
    const float* row = q + b * DIM;
    float s = 0.f;
    for (int i = threadIdx.x; i < DIM; i += 128) { float v = row[i]; s += v * v; }
    __shared__ float red[4];
    __shared__ float sval[2];
    #pragma unroll
    for (int o = 16; o; o >>= 1) s += __shfl_xor_sync(0xffffffffu, s, o);
    if ((threadIdx.x & 31) == 0) red[threadIdx.x >> 5] = s;
    __syncthreads();
    if (threadIdx.x == 0)
        sval[0] = 1.0f / fmaxf(sqrtf(red[0] + red[1] + red[2] + red[3]), 1e-12f);
    __syncthreads();
    float sc = sval[0];
    float ma = 0.f;
    for (int i = threadIdx.x; i < DIM; i += 128) {
        float v = row[i] * sc;
        g_qn[b * DIM + i] = v;
        ma = fmaxf(ma, fabsf(v));
    }
    #pragma unroll
    for (int o = 16; o; o >>= 1) ma = fmaxf(ma, __shfl_xor_sync(0xffffffffu, ma, o));
    if ((threadIdx.x & 31) == 0) red[threadIdx.x >> 5] = ma;
    __syncthreads();
    if (threadIdx.x == 0)
        sval[1] = 127.0f / fmaxf(fmaxf(fmaxf(red[0], red[1]), fmaxf(red[2], red[3])), 1e-20f);
    __syncthreads();
    float qs = sval[1];
    for (int i = threadIdx.x; i < DIM; i += 128) {
        int iv = __float2int_rn(g_qn[b * DIM + i] * qs);
        g_q8[b * DIM + i] = (int8_t)max(-127, min(127, iv));
    }
}

// ---------------- kernel 1b: E, D -> int8 with per-row scales ----------------
// one warp per cube row; block = 256 (8 warps)
__global__ __launch_bounds__(256) void quant_ed_kernel(const float* __restrict__ emb,
                                                       const float* __restrict__ dual) {
    int row = blockIdx.x * 8 + (threadIdx.x >> 5);
    int lane = threadIdx.x & 31;
    if (row >= NCUBES) return;
    const float4* e4 = (const float4*)(emb  + (size_t)row * DIM);
    const float4* d4 = (const float4*)(dual + (size_t)row * DIM);
    float4 ev[3], dv[3];
    float mae = 0.f, mad = 0.f;
    #pragma unroll
    for (int i = 0; i < 3; i++) {
        ev[i] = e4[i * 32 + lane];
        dv[i] = d4[i * 32 + lane];
        mae = fmaxf(mae, fmaxf(fmaxf(fabsf(ev[i].x), fabsf(ev[i].y)),
                               fmaxf(fabsf(ev[i].z), fabsf(ev[i].w))));
        mad = fmaxf(mad, fmaxf(fmaxf(fabsf(dv[i].x), fabsf(dv[i].y)),
                               fmaxf(fabsf(dv[i].z), fabsf(dv[i].w))));
    }
    #pragma unroll
    for (int o = 16; o; o >>= 1) {
        mae = fmaxf(mae, __shfl_xor_sync(0xffffffffu, mae, o));
        mad = fmaxf(mad, __shfl_xor_sync(0xffffffffu, mad, o));
    }
    float qe = 127.0f / fmaxf(mae, 1e-20f);
    float qd = 127.0f / fmaxf(mad, 1e-20f);
    if (lane == 0) { g_se[row] = mae / 127.0f; g_sd[row] = mad / 127.0f; }
    char4* e8 = (char4*)(g_e8 + (size_t)row * DIM);
    char4* d8 = (char4*)(g_d8 + (size_t)row * DIM);
    #pragma unroll
    for (int i = 0; i < 3; i++) {
        char4 c;
        c.x = (char)max(-127, min(127, __float2int_rn(ev[i].x * qe)));
        c.y = (char)max(-127, min(127, __float2int_rn(ev[i].y * qe)));
        c.z = (char)max(-127, min(127, __float2int_rn(ev[i].z * qe)));
        c.w = (char)max(-127, min(127, __float2int_rn(ev[i].w * qe)));
        e8[i * 32 + lane] = c;
        c.x = (char)max(-127, min(127, __float2int_rn(dv[i].x * qd)));
        c.y = (char)max(-127, min(127, __float2int_rn(dv[i].y * qd)));
        c.z = (char)max(-127, min(127, __float2int_rn(dv[i].z * qd)));
        c.w = (char)max(-127, min(127, __float2int_rn(dv[i].w * qd)));
        d8[i * 32 + lane] = c;
    }
}

// ---------------- kernel 2: int8 IMMA approx scores + fused per-chunk top-16 ----------------
// grid = (BTILES, NCHUNKS) = (8, 64), block = 512 (16 warps, 4x4), 4-stage cp.async pipeline
__global__ __launch_bounds__(NTHREADS, 1) void score_kernel() {
    extern __shared__ char sm[];
    const uint32_t smb = smem_u32(sm);
    float (*scb)[SC_PITCH] = (float(*)[SC_PITCH])(sm + OFF_SC);   // [query][cube]
    float* se_s = (float*)(sm + OFF_SE);
    float* sd_s = (float*)(sm + OFF_SD);
    float (*lv)[LVP] = (float(*)[LVP])(sm + OFF_LV);
    int   (*li)[LVP] = (int  (*)[LVP])(sm + OFF_LI);

    const int tid    = threadIdx.x;
    const int lane   = tid & 31;
    const int warp   = tid >> 5;
    const int warp_q = warp >> 2;          // 0..3  (32 q rows each)
    const int warp_c = warp & 3;           // 0..3  (32 c cols each)
    const int qbase  = blockIdx.x * BT;
    const int nbase  = blockIdx.y * NCHUNK;

    // ldmatrix lane addressing (byte-scaled analog of validated fp16 pattern)
    const int aRow   = (lane & 15);
    const int aColB  = (lane >> 4) * 16;                  // bytes
    const int bRow   = (lane & 7) + ((lane >> 4) & 1) * 8;
    const int bColB  = ((lane >> 3) & 1) * 16;            // bytes

    if (tid < BT) {
        #pragma unroll
        for (int k = 0; k < TOPK; k++) { lv[tid][k] = -FLT_MAX; li[tid][k] = 0; }
    }
    // load per-chunk dequant scales (2048 each)
    for (int l = tid; l < NCHUNK; l += NTHREADS) {
        se_s[l] = g_se[nbase + l];
        sd_s[l] = g_sd[nbase + l];
    }
    __syncthreads();

    // ---- async stage loader: Q 512 + E 512 + D 512 chunks of 16B = 3/thread ----
    auto load_stage = [&](int T) {
        const int nt = T / NKT, kt = T % NKT;
        const int cbase = nbase + nt * CT;
        const int koff  = kt * KT;
        const uint32_t sb = smb + (T & (NSTAGE - 1)) * STAGE;
        {   // Q: 128 rows x 4 x 16B
            int r = tid >> 2, ch = (tid & 3) * 16;
            cp16(sb + r * PITCHB + ch, &g_q8[(qbase + r) * DIM + koff + ch]);
        }
        {   // E
            int r = tid >> 2, ch = (tid & 3) * 16;
            cp16(sb + ST_Q + r * PITCHB + ch, &g_e8[(size_t)(cbase + r) * DIM + koff + ch]);
        }
        {   // D
            int r = tid >> 2, ch = (tid & 3) * 16;
            cp16(sb + ST_Q + ST_ED + r * PITCHB + ch, &g_d8[(size_t)(cbase + r) * DIM + koff + ch]);
        }
        cp_commit();
    };

    int accE[2][4][4], accD[2][4][4];

    load_stage(0);
    load_stage(1);
    load_stage(2);

    for (int T = 0; T < NTT; T++) {
        const int s  = T & (NSTAGE - 1);
        const int nt = T / NKT, kt = T % NKT;

        cp_wait<2>();        // stage T resident
        __syncthreads();     // all warps done with compute T-1 (frees buffer (T+3)&3)

        if (T + 3 < NTT) load_stage(T + 3);   // overlaps compute below

        if (kt == 0) {
            #pragma unroll
            for (int mi = 0; mi < 2; mi++)
                #pragma unroll
                for (int ni = 0; ni < 4; ni++)
                    #pragma unroll
                    for (int r = 0; r < 4; r++) { accE[mi][ni][r] = 0; accD[mi][ni][r] = 0; }
        }

        // ---- compute on stage s: 2 k-steps of 32 int8 ----
        {
            const uint32_t sQ = smb + s * STAGE;
            const uint32_t sE = sQ + ST_Q;
            const uint32_t sD = sE + ST_ED;
            #pragma unroll
            for (int ks = 0; ks < 2; ks++) {
                uint32_t aQ[2][4];
                #pragma unroll
                for (int mi = 0; mi < 2; mi++)
                    ldsm4(aQ[mi], sQ + (warp_q * 32 + mi * 16 + aRow) * PITCHB + ks * 32 + aColB);
                #pragma unroll
                for (int j = 0; j < 2; j++) {
                    uint32_t off = (warp_c * 32 + j * 16 + bRow) * PITCHB + ks * 32 + bColB;
                    uint32_t bE[4], bD[4];
                    ldsm4(bE, sE + off);
                    ldsm4(bD, sD + off);
                    #pragma unroll
                    for (int mi = 0; mi < 2; mi++) {
                        #pragma unroll
                        for (int p = 0; p < 2; p++) {
                            mma16832s8(accE[mi][j * 2 + p], aQ[mi], &bE[2 * p]);
                            mma16832s8(accD[mi][j * 2 + p], aQ[mi], &bD[2 * p]);
                        }
                    }
                }
            }
        }

        if (kt == NKT - 1) {
            const int cbase = nbase + nt * CT;
            // dequant (per-cube scales; per-query scale cancels in ranking) + relu + combine
            {
                int m_off = lane >> 2, n_off = (lane & 3) * 2;
                #pragma unroll
                for (int mi = 0; mi < 2; mi++) {
                    #pragma unroll
                    for (int ni = 0; ni < 4; ni++) {
                        int m = warp_q * 32 + mi * 16 + m_off;
                        int n = warp_c * 32 + ni * 8 + n_off;
                        int nl0 = nt * CT + n, nl1 = nl0 + 1;
                        float se0 = se_s[nl0], se1 = se_s[nl1];
                        float sd0 = sd_s[nl0], sd1 = sd_s[nl1];
                        scb[m    ][n    ] = (float)accE[mi][ni][0] * se0 + 0.35f * sd0 * (float)max(accD[mi][ni][0], 0);
                        scb[m    ][n + 1] = (float)accE[mi][ni][1] * se1 + 0.35f * sd1 * (float)max(accD[mi][ni][1], 0);
                        scb[m + 8][n    ] = (float)accE[mi][ni][2] * se0 + 0.35f * sd0 * (float)max(accD[mi][ni][2], 0);
                        scb[m + 8][n + 1] = (float)accE[mi][ni][3] * se1 + 0.35f * sd1 * (float)max(accD[mi][ni][3], 0);
                    }
                }
            }
            __syncthreads();   // score writes visible to scanners
            if (tid < BT) {    // vectorized per-query scan
                float* mylv = lv[tid];
                int*   myli = li[tid];
                float  thr  = mylv[0];
                const float4* rowp = (const float4*)&scb[tid][0];
                #pragma unroll 8
                for (int c4 = 0; c4 < CT / 4; c4++) {
                    float4 v = rowp[c4];
                    float vals[4] = {v.x, v.y, v.z, v.w};
                    #pragma unroll
                    for (int u = 0; u < 4; u++) {
                        float sv = vals[u];
                        if (sv > thr) {
                            int j = 0;
                            while (j < TOPK - 1 && mylv[j + 1] < sv) {
                                mylv[j] = mylv[j + 1];
                                myli[j] = myli[j + 1];
                                j++;
                            }
                            mylv[j] = sv;
                            myli[j] = cbase + c4 * 4 + u;
                            thr = mylv[0];
                        }
                    }
                }
            }
        }
    }

    __syncthreads();
    if (tid < BT) {
        int q = qbase + tid;
        int base = (q * NCHUNKS + blockIdx.y) * TOPK;
        #pragma unroll
        for (int k = 0; k < TOPK; k++) {
            g_cand_v[base + k] = lv[tid][TOPK - 1 - k];
            g_cand_i[base + k] = li[tid][TOPK - 1 - k];
        }
    }
}

// ---------------- kernel 3: merge, exact rescore, final top-16 ----------------
__global__ __launch_bounds__(256) void merge_rescore_kernel(float* __restrict__ out, int out_size,
                                                            const float* __restrict__ emb,
                                                            const float* __restrict__ dual) {
    const int q = blockIdx.x;
    const int tid = threadIdx.x;
    const int lane = tid & 31;
    const int warp = tid >> 5;
    const int NC = NCHUNKS * TOPK;   // 1024
    __shared__ float av[NCHUNKS * TOPK];
    __shared__ int   ai[NCHUNKS * TOPK];
    __shared__ float qv[DIM];
    __shared__ int   cidx[RESCORE];
    __shared__ float cs[RESCORE];
    __shared__ float bwv[8];
    __shared__ int   bws[8];

    for (int l = tid; l < NC; l += 256) {
        av[l] = g_cand_v[q * NC + l];
        ai[l] = g_cand_i[q * NC + l];
    }
    for (int l = tid; l < DIM; l += 256) qv[l] = g_qn[q * DIM + l];
    __syncthreads();

    // select top-RESCORE candidates by approx score
    for (int k = 0; k < RESCORE; k++) {
        float bv = -FLT_MAX;
        int   bs = 0x7fffffff;
        for (int l = tid; l < NC; l += 256) {
            float vv = av[l];
            if (vv > bv || (vv == bv && l < bs)) { bv = vv; bs = l; }
        }
        #pragma unroll
        for (int o = 16; o; o >>= 1) {
            float ov = __shfl_xor_sync(0xffffffffu, bv, o);
            int   os = __shfl_xor_sync(0xffffffffu, bs, o);
            if (ov > bv || (ov == bv && os < bs)) { bv = ov; bs = os; }
        }
        if (lane == 0) { bwv[warp] = bv; bws[warp] = bs; }
        __syncthreads();
        if (tid == 0) {
            float fv = bwv[0]; int fs = bws[0];
            #pragma unroll
            for (int w = 1; w < 8; w++)
                if (bwv[w] > fv || (bwv[w] == fv && bws[w] < fs)) { fv = bwv[w]; fs = bws[w]; }
            cidx[k] = ai[fs];
            av[fs] = -FLT_MAX;
        }
        __syncthreads();
    }

    // exact fp32 rescore: one warp per candidate
    for (int c = warp; c < RESCORE; c += 8) {
        int idx = cidx[c];
        const float* e = emb  + (size_t)idx * DIM;
        const float* d = dual + (size_t)idx * DIM;
        float de = 0.f, dd = 0.f;
        for (int t = lane; t < DIM; t += 32) {
            float qq = qv[t];
            de += qq * e[t];
            dd += qq * d[t];
        }
        #pragma unroll
        for (int o = 16; o; o >>= 1) {
            de += __shfl_xor_sync(0xffffffffu, de, o);
            dd += __shfl_xor_sync(0xffffffffu, dd, o);
        }
        if (lane == 0) cs[c] = de + 0.35f * fmaxf(dd, 0.f);
    }
    __syncthreads();

    // final exact top-16 with lower-index tie-break
    if (tid == 0) {
        bool used[RESCORE];
        #pragma unroll
        for (int c = 0; c < RESCORE; c++) used[c] = false;
        for (int k = 0; k < TOPK; k++) {
            float bv = -FLT_MAX;
            int   bi = 0x7fffffff, bs = 0;
            for (int c = 0; c < RESCORE; c++) {
                if (used[c]) continue;
                float vv = cs[c];
                int   ii = cidx[c];
                if (vv > bv || (vv == bv && ii < bi)) { bv = vv; bi = ii; bs = c; }
            }
            used[bs] = true;
            out[q * TOPK + k] = bv;
            if (out_size >= 2 * BATCH * TOPK)
                out[BATCH * TOPK + q * TOPK + k] = (float)bi;
        }
    }
}

// ---------------- launch ----------------
extern "C" void kernel_launch(void* const* d_in, const int* in_sizes, int n_in,
                              void* d_out, int out_size) {
    const float* query = (const float*)d_in[0];
    const float* emb   = (const float*)d_in[1];
    const float* dual  = (const float*)d_in[2];
    float* out = (float*)d_out;

    cudaFuncSetAttribute(score_kernel,
                         cudaFuncAttributeMaxDynamicSharedMemorySize, SMEM_SZ);

    norm_q_kernel<<<BATCH, 128>>>(query);
    quant_ed_kernel<<<NCUBES / 8, 256>>>(emb, dual);

    dim3 grid(BTILES, NCHUNKS);
    score_kernel<<<grid, NTHREADS, SMEM_SZ>>>();

    merge_rescore_kernel<<<BATCH, 256>>>(out, out_size, emb, dual);
}

// round 15
// speedup vs baseline: 1.7156x; 1.7156x over previous
#include <cuda_runtime.h>
#include <cuda_fp16.h>
#include <float.h>
#include <math.h>
#include <stdint.h>

#define BATCH   1024
#define DIM     384
#define NCUBES  131072
#define TOPK    16

#define BT      128             // queries per CTA
#define CT      64              // cubes per n-tile
#define KT      32              // halfs per k tile
#define NKT     (DIM/KT)        // 12
#define NCHUNK  1024            // cubes per CTA chunk
#define NTILES  (NCHUNK/CT)     // 16
#define NCHUNKS (NCUBES/NCHUNK) // 128
#define BTILES  (BATCH/BT)      // 8
#define NTT     (NTILES*NKT)    // 192
#define NTHREADS 256
#define LVP     17
#define RESCORE 32

#define PITCH   40              // smem row pitch in halfs (32 + 8 pad)

// ---- stage layout (bytes) ----
#define ST_Q    (BT*PITCH*2)          // 10240
#define ST_ED   (CT*PITCH*2)          // 5120
#define STAGE   (ST_Q + 2*ST_ED)      // 20480
#define OFF_SC  (2*STAGE)             // 40960
#define SC_PITCH 68                   // floats per query row (64 + 4 pad)
#define OFF_LV  (OFF_SC + BT*SC_PITCH*4)   // 75776
#define OFF_LI  (OFF_LV + BT*LVP*4)        // 84480
#define SMEM_SZ (OFF_LI + BT*LVP*4)        // 93184  (x2 CTAs = 186368 < 227KB)

// ---------------- device scratch ----------------
__device__ float  g_qn[BATCH * DIM];
__device__ __half g_Qh[BATCH * DIM];
__device__ __half g_Eh[NCUBES * DIM];
__device__ __half g_Dh[NCUBES * DIM];
__device__ float  g_cand_v[BATCH * NCHUNKS * TOPK];
__device__ int    g_cand_i[BATCH * NCHUNKS * TOPK];

// ---------------- PTX helpers ----------------
__device__ __forceinline__ uint32_t smem_u32(const void* p) {
    uint32_t a;
    asm("{ .reg .u64 t; cvta.to.shared.u64 t, %1; cvt.u32.u64 %0, t; }" : "=r"(a) : "l"(p));
    return a;
}
__device__ __forceinline__ void cp16(uint32_t s, const void* g) {
    asm volatile("cp.async.cg.shared.global [%0], [%1], 16;" :: "r"(s), "l"(g));
}
__device__ __forceinline__ void cp_commit() {
    asm volatile("cp.async.commit_group;");
}
template <int N> __device__ __forceinline__ void cp_wait() {
    asm volatile("cp.async.wait_group %0;" :: "n"(N));
}
__device__ __forceinline__ void ldsm4(uint32_t* r, uint32_t addr) {
    asm volatile("ldmatrix.sync.aligned.m8n8.x4.shared.b16 {%0,%1,%2,%3}, [%4];"
                 : "=r"(r[0]), "=r"(r[1]), "=r"(r[2]), "=r"(r[3]) : "r"(addr));
}
__device__ __forceinline__ void mma16816(float* d, const uint32_t* a, const uint32_t* b) {
    asm volatile("mma.sync.aligned.m16n8k16.row.col.f32.f16.f16.f32 "
                 "{%0,%1,%2,%3}, {%4,%5,%6,%7}, {%8,%9}, {%0,%1,%2,%3};"
                 : "+f"(d[0]), "+f"(d[1]), "+f"(d[2]), "+f"(d[3])
                 : "r"(a[0]), "r"(a[1]), "r"(a[2]), "r"(a[3]),
                   "r"(b[0]), "r"(b[1]));
}

// ---------------- kernel 1: normalize queries (fp32 + fp16) ----------------
__global__ __launch_bounds__(128) void norm_q_kernel(const float* __restrict__ q) {
    int b = blockIdx.x;
    const float* row = q + b * DIM;
    float s = 0.f;
    for (int i = threadIdx.x; i < DIM; i += 128) { float v = row[i]; s += v * v; }
    __shared__ float red[4];
    #pragma unroll
    for (int o = 16; o; o >>= 1) s += __shfl_xor_sync(0xffffffffu, s, o);
    if ((threadIdx.x & 31) == 0) red[threadIdx.x >> 5] = s;
    __syncthreads();
    if (threadIdx.x == 0) {
        float t = red[0] + red[1] + red[2] + red[3];
        red[0] = 1.0f / fmaxf(sqrtf(t), 1e-12f);
    }
    __syncthreads();
    float sc = red[0];
    for (int i = threadIdx.x; i < DIM; i += 128) {
        float v = row[i] * sc;
        g_qn[b * DIM + i] = v;
        g_Qh[b * DIM + i] = __float2half_rn(v);
    }
}

// ---------------- kernel 1b: E, D -> fp16 ----------------
__global__ __launch_bounds__(256) void half_ed_kernel(const float* __restrict__ emb,
                                                      const float* __restrict__ dual) {
    const int total4 = NCUBES * DIM / 4;
    for (int i = blockIdx.x * blockDim.x + threadIdx.x; i < total4;
         i += gridDim.x * blockDim.x) {
        float4 v = ((const float4*)emb)[i];
        uint2 h;
        ((__half2*)&h)[0] = __halves2half2(__float2half_rn(v.x), __float2half_rn(v.y));
        ((__half2*)&h)[1] = __halves2half2(__float2half_rn(v.z), __float2half_rn(v.w));
        ((uint2*)g_Eh)[i] = h;
        float4 w = ((const float4*)dual)[i];
        ((__half2*)&h)[0] = __halves2half2(__float2half_rn(w.x), __float2half_rn(w.y));
        ((__half2*)&h)[1] = __halves2half2(__float2half_rn(w.z), __float2half_rn(w.w));
        ((uint2*)g_Dh)[i] = h;
    }
}

// ---------------- kernel 2: fp16 HMMA approx scores + fused per-chunk top-16 ----------------
// grid = (BTILES, NCHUNKS) = (8, 128), block = 256 (8 warps, 4x2), 2 CTAs/SM,
// 2-stage cp.async pipeline (race-free ordering: wait -> sync -> load next)
__global__ __launch_bounds__(NTHREADS, 2) void score_kernel() {
    extern __shared__ char sm[];
    const uint32_t smb = smem_u32(sm);
    float (*scb)[SC_PITCH] = (float(*)[SC_PITCH])(sm + OFF_SC);   // [query][cube]
    float (*lv)[LVP] = (float(*)[LVP])(sm + OFF_LV);
    int   (*li)[LVP] = (int  (*)[LVP])(sm + OFF_LI);

    const int tid    = threadIdx.x;
    const int lane   = tid & 31;
    const int warp   = tid >> 5;
    const int warp_q = warp >> 1;          // 0..3  (32 q rows each)
    const int warp_c = warp & 1;           // 0..1  (32 c cols each)
    const int qbase  = blockIdx.x * BT;
    const int nbase  = blockIdx.y * NCHUNK;

    // ldmatrix lane addressing (validated R4/R7/R8/R11)
    const int aRow = (lane & 15);
    const int aCol = (lane >> 4) * 8;
    const int bRow = (lane & 7) + ((lane >> 4) & 1) * 8;
    const int bCol = ((lane >> 3) & 1) * 8;

    if (tid < BT) {
        #pragma unroll
        for (int k = 0; k < TOPK; k++) { lv[tid][k] = -FLT_MAX; li[tid][k] = 0; }
    }
    __syncthreads();

    // ---- async stage loader: Q 512 + E 256 + D 256 chunks of 16B = 4/thread ----
    auto load_stage = [&](int T) {
        const int nt = T / NKT, kt = T % NKT;
        const int cbase = nbase + nt * CT;
        const int koff  = kt * KT;
        const uint32_t sb = smb + (T & 1) * STAGE;
        #pragma unroll
        for (int t = 0; t < 2; t++) {   // Q: 128 rows x 4 chunks
            int idx = tid + t * NTHREADS;
            int r = idx >> 2, ch = (idx & 3) * 8;
            cp16(sb + (r * PITCH + ch) * 2, &g_Qh[(qbase + r) * DIM + koff + ch]);
        }
        {   // E: 64 rows x 4 chunks
            int r = tid >> 2, ch = (tid & 3) * 8;
            cp16(sb + ST_Q + (r * PITCH + ch) * 2, &g_Eh[(cbase + r) * DIM + koff + ch]);
        }
        {   // D: 64 rows x 4 chunks
            int r = tid >> 2, ch = (tid & 3) * 8;
            cp16(sb + ST_Q + ST_ED + (r * PITCH + ch) * 2, &g_Dh[(cbase + r) * DIM + koff + ch]);
        }
        cp_commit();
    };

    float accE[2][4][4], accD[2][4][4];

    load_stage(0);

    for (int T = 0; T < NTT; T++) {
        const int s  = T & 1;
        const int nt = T / NKT, kt = T % NKT;

        cp_wait<0>();        // stage T resident
        __syncthreads();     // all warps done with buffer s^1 (iter T-1)

        if (T + 1 < NTT) load_stage(T + 1);   // fills s^1; overlaps compute below

        if (kt == 0) {
            #pragma unroll
            for (int mi = 0; mi < 2; mi++)
                #pragma unroll
                for (int ni = 0; ni < 4; ni++)
                    #pragma unroll
                    for (int r = 0; r < 4; r++) { accE[mi][ni][r] = 0.f; accD[mi][ni][r] = 0.f; }
        }

        // ---- compute on stage s: 2 k-slices of 16 ----
        {
            const uint32_t sQ = smb + s * STAGE;
            const uint32_t sE = sQ + ST_Q;
            const uint32_t sD = sE + ST_ED;
            #pragma unroll
            for (int ks = 0; ks < 2; ks++) {
                uint32_t aH[2][4];
                #pragma unroll
                for (int mi = 0; mi < 2; mi++)
                    ldsm4(aH[mi], sQ + ((warp_q * 32 + mi * 16 + aRow) * PITCH + ks * 16 + aCol) * 2);
                #pragma unroll
                for (int j = 0; j < 2; j++) {
                    uint32_t off = ((warp_c * 32 + j * 16 + bRow) * PITCH + ks * 16 + bCol) * 2;
                    uint32_t bE[4], bD[4];
                    ldsm4(bE, sE + off);
                    ldsm4(bD, sD + off);
                    #pragma unroll
                    for (int mi = 0; mi < 2; mi++) {
                        #pragma unroll
                        for (int p = 0; p < 2; p++) {
                            mma16816(accE[mi][j * 2 + p], aH[mi], &bE[2 * p]);
                            mma16816(accD[mi][j * 2 + p], aH[mi], &bD[2 * p]);
                        }
                    }
                }
            }
        }

        if (kt == NKT - 1) {
            const int cbase = nbase + nt * CT;
            // write combined scores TRANSPOSED: scb[query][cube]
            {
                int m_off = lane >> 2, n_off = (lane & 3) * 2;
                #pragma unroll
                for (int mi = 0; mi < 2; mi++) {
                    #pragma unroll
                    for (int ni = 0; ni < 4; ni++) {
                        int m = warp_q * 32 + mi * 16 + m_off;
                        int n = warp_c * 32 + ni * 8 + n_off;
                        scb[m    ][n    ] = accE[mi][ni][0] + 0.35f * fmaxf(accD[mi][ni][0], 0.f);
                        scb[m    ][n + 1] = accE[mi][ni][1] + 0.35f * fmaxf(accD[mi][ni][1], 0.f);
                        scb[m + 8][n    ] = accE[mi][ni][2] + 0.35f * fmaxf(accD[mi][ni][2], 0.f);
                        scb[m + 8][n + 1] = accE[mi][ni][3] + 0.35f * fmaxf(accD[mi][ni][3], 0.f);
                    }
                }
            }
            __syncthreads();   // score writes visible to scanners
            if (tid < BT) {    // vectorized per-query scan: 16 float4
                float* mylv = lv[tid];
                int*   myli = li[tid];
                float  thr  = mylv[0];
                const float4* rowp = (const float4*)&scb[tid][0];
                #pragma unroll 4
                for (int c4 = 0; c4 < CT / 4; c4++) {
                    float4 v = rowp[c4];
                    float vals[4] = {v.x, v.y, v.z, v.w};
                    #pragma unroll
                    for (int u = 0; u < 4; u++) {
                        float sv = vals[u];
                        if (sv > thr) {
                            int j = 0;
                            while (j < TOPK - 1 && mylv[j + 1] < sv) {
                                mylv[j] = mylv[j + 1];
                                myli[j] = myli[j + 1];
                                j++;
                            }
                            mylv[j] = sv;
                            myli[j] = cbase + c4 * 4 + u;
                            thr = mylv[0];
                        }
                    }
                }
            }
        }
    }

    __syncthreads();
    if (tid < BT) {
        int q = qbase + tid;
        int base = (q * NCHUNKS + blockIdx.y) * TOPK;
        #pragma unroll
        for (int k = 0; k < TOPK; k++) {
            g_cand_v[base + k] = lv[tid][TOPK - 1 - k];
            g_cand_i[base + k] = li[tid][TOPK - 1 - k];
        }
    }
}

// ---------------- kernel 3: merge, exact rescore, final top-16 ----------------
__global__ __launch_bounds__(256) void merge_rescore_kernel(float* __restrict__ out, int out_size,
                                                            const float* __restrict__ emb,
                                                            const float* __restrict__ dual) {
    const int q = blockIdx.x;
    const int tid = threadIdx.x;
    const int lane = tid & 31;
    const int warp = tid >> 5;
    const int NC = NCHUNKS * TOPK;   // 2048
    __shared__ float av[NCHUNKS * TOPK];
    __shared__ int   ai[NCHUNKS * TOPK];
    __shared__ float qv[DIM];
    __shared__ int   cidx[RESCORE];
    __shared__ float cs[RESCORE];
    __shared__ float bwv[8];
    __shared__ int   bws[8];

    for (int l = tid; l < NC; l += 256) {
        av[l] = g_cand_v[q * NC + l];
        ai[l] = g_cand_i[q * NC + l];
    }
    for (int l = tid; l < DIM; l += 256) qv[l] = g_qn[q * DIM + l];
    __syncthreads();

    for (int k = 0; k < RESCORE; k++) {
        float bv = -FLT_MAX;
        int   bs = 0x7fffffff;
        for (int l = tid; l < NC; l += 256) {
            float vv = av[l];
            if (vv > bv || (vv == bv && l < bs)) { bv = vv; bs = l; }
        }
        #pragma unroll
        for (int o = 16; o; o >>= 1) {
            float ov = __shfl_xor_sync(0xffffffffu, bv, o);
            int   os = __shfl_xor_sync(0xffffffffu, bs, o);
            if (ov > bv || (ov == bv && os < bs)) { bv = ov; bs = os; }
        }
        if (lane == 0) { bwv[warp] = bv; bws[warp] = bs; }
        __syncthreads();
        if (tid == 0) {
            float fv = bwv[0]; int fs = bws[0];
            #pragma unroll
            for (int w = 1; w < 8; w++)
                if (bwv[w] > fv || (bwv[w] == fv && bws[w] < fs)) { fv = bwv[w]; fs = bws[w]; }
            cidx[k] = ai[fs];
            av[fs] = -FLT_MAX;
        }
        __syncthreads();
    }

    for (int c = warp; c < RESCORE; c += 8) {
        int idx = cidx[c];
        const float* e = emb  + (size_t)idx * DIM;
        const float* d = dual + (size_t)idx * DIM;
        float de = 0.f, dd = 0.f;
        for (int t = lane; t < DIM; t += 32) {
            float qq = qv[t];
            de += qq * e[t];
            dd += qq * d[t];
        }
        #pragma unroll
        for (int o = 16; o; o >>= 1) {
            de += __shfl_xor_sync(0xffffffffu, de, o);
            dd += __shfl_xor_sync(0xffffffffu, dd, o);
        }
        if (lane == 0) cs[c] = de + 0.35f * fmaxf(dd, 0.f);
    }
    __syncthreads();

    if (tid == 0) {
        bool used[RESCORE];
        #pragma unroll
        for (int c = 0; c < RESCORE; c++) used[c] = false;
        for (int k = 0; k < TOPK; k++) {
            float bv = -FLT_MAX;
            int   bi = 0x7fffffff, bs = 0;
            for (int c = 0; c < RESCORE; c++) {
                if (used[c]) continue;
                float vv = cs[c];
                int   ii = cidx[c];
                if (vv > bv || (vv == bv && ii < bi)) { bv = vv; bi = ii; bs = c; }
            }
            used[bs] = true;
            out[q * TOPK + k] = bv;
            if (out_size >= 2 * BATCH * TOPK)
                out[BATCH * TOPK + q * TOPK + k] = (float)bi;
        }
    }
}

// ---------------- launch ----------------
extern "C" void kernel_launch(void* const* d_in, const int* in_sizes, int n_in,
                              void* d_out, int out_size) {
    const float* query = (const float*)d_in[0];
    const float* emb   = (const float*)d_in[1];
    const float* dual  = (const float*)d_in[2];
    float* out = (float*)d_out;

    cudaFuncSetAttribute(score_kernel,
                         cudaFuncAttributeMaxDynamicSharedMemorySize, SMEM_SZ);

    norm_q_kernel<<<BATCH, 128>>>(query);
    half_ed_kernel<<<8192, 256>>>(emb, dual);

    dim3 grid(BTILES, NCHUNKS);
    score_kernel<<<grid, NTHREADS, SMEM_SZ>>>();

    merge_rescore_kernel<<<BATCH, 256>>>(out, out_size, emb, dual);
}